// round 1
// baseline (speedup 1.0000x reference)
#include <cuda_runtime.h>
#include <cuda_bf16.h>

#define NN 100000
#define EE 1200000
#define HH 64
#define EDD 16
#define LL 3
#define GG 1000

// ---------------- device scratch (no allocation allowed) ----------------
__device__ __align__(256) float g_h[NN * HH];      // current node features
__device__ __align__(256) float g_S[NN * HH];      // scatter accumulator segsum(h[src], dst)
__device__ __align__(256) float g_T[NN * HH];      // t = relu(...)
__device__ __align__(256) float g_tmp[NN * HH];    // pre-norm layer output
__device__ __align__(256) float g_aggea[NN * EDD]; // segsum(edge_attr, dst)  (layer-invariant)
__device__ __align__(256) float g_deg[NN];         // in-degree               (layer-invariant)
__device__ __align__(256) float g_cnt[GG];         // nodes per graph         (layer-invariant)
__device__ __align__(256) float g_sum[GG * HH];
__device__ __align__(256) float g_sumsq[GG * HH];
__device__ __align__(256) float g_mean[GG * HH];
__device__ __align__(256) float g_istd[GG * HH];
__device__ __align__(256) float g_A[HH * HH];      // Wn @ W1a
__device__ __align__(256) float g_B[HH * HH];      // Wn @ W1b
__device__ __align__(256) float g_C[EDD * HH];     // We @ W1b
__device__ __align__(256) float g_c1[HH];          // bn@W1a + b1
__device__ __align__(256) float g_c2[HH];          // (bn+be)@W1b

// vector float atomic reduction (sm_90+)
__device__ __forceinline__ void red4(float* p, float4 v) {
    asm volatile("red.global.add.v4.f32 [%0], {%1,%2,%3,%4};"
                 :: "l"(p), "f"(v.x), "f"(v.y), "f"(v.z), "f"(v.w) : "memory");
}

// ---------------- once-per-call precompute ----------------
__global__ void k_zero_init() {
    const int tot = NN * EDD + NN + GG;
    for (int i = blockIdx.x * blockDim.x + threadIdx.x; i < tot; i += gridDim.x * blockDim.x) {
        if (i < NN * EDD)           g_aggea[i] = 0.f;
        else if (i < NN * EDD + NN) g_deg[i - NN * EDD] = 0.f;
        else                        g_cnt[i - NN * EDD - NN] = 0.f;
    }
}

// agg_ea[dst] += edge_attr[e]; deg[dst] += 1    (thread = (edge, 4-float chunk))
__global__ void k_edge_pre(const int* __restrict__ ei, const float* __restrict__ ea) {
    int t = blockIdx.x * 256 + threadIdx.x;
    if (t >= EE * 4) return;
    int e = t >> 2, q = t & 3;
    int d = __ldg(ei + EE + e);
    float4 v = __ldg((const float4*)(ea + (size_t)e * EDD) + q);
    red4(&g_aggea[(size_t)d * EDD + q * 4], v);
    if (q == 0) atomicAdd(&g_deg[d], 1.0f);
}

__global__ void k_cnt(const int* __restrict__ batch) {
    int n = blockIdx.x * blockDim.x + threadIdx.x;
    if (n < NN) atomicAdd(&g_cnt[__ldg(batch + n)], 1.0f);
}

// per-layer fused-weight precompute: A=Wn@W1a, B=Wn@W1b, C=We@W1b, c1, c2
__global__ void k_pre(const float* __restrict__ nodeW, const float* __restrict__ edgeW,
                      const float* __restrict__ nodeb, const float* __restrict__ edgeb,
                      const float* __restrict__ m1W,   const float* __restrict__ m1b) {
    int j = threadIdx.x;
    int kb = blockIdx.x;
    if (kb < 64) {
        float a = 0.f, b = 0.f;
        for (int m = 0; m < 64; m++) {
            float wn = __ldg(nodeW + kb * 64 + m);
            a = fmaf(wn, __ldg(m1W + m * 64 + j), a);
            b = fmaf(wn, __ldg(m1W + (64 + m) * 64 + j), b);
        }
        g_A[kb * 64 + j] = a;
        g_B[kb * 64 + j] = b;
    } else if (kb < 80) {
        int k = kb - 64;
        float c = 0.f;
        for (int m = 0; m < 64; m++)
            c = fmaf(__ldg(edgeW + k * 64 + m), __ldg(m1W + (64 + m) * 64 + j), c);
        g_C[k * 64 + j] = c;
    } else {
        float s1 = __ldg(m1b + j), s2 = 0.f;
        for (int m = 0; m < 64; m++) {
            s1 = fmaf(__ldg(nodeb + m), __ldg(m1W + m * 64 + j), s1);
            s2 = fmaf(__ldg(nodeb + m) + __ldg(edgeb + m), __ldg(m1W + (64 + m) * 64 + j), s2);
        }
        g_c1[j] = s1;
        g_c2[j] = s2;
    }
}

__global__ void k_zero_layer() {
    const int tot = NN * HH + 2 * GG * HH;
    for (int i = blockIdx.x * blockDim.x + threadIdx.x; i < tot; i += gridDim.x * blockDim.x) {
        if (i < NN * HH)               g_S[i] = 0.f;
        else if (i < NN * HH + GG * HH) g_sum[i - NN * HH] = 0.f;
        else                           g_sumsq[i - NN * HH - GG * HH] = 0.f;
    }
}

// ---------------- encoder: h = x @ enc_W + enc_b ----------------
__global__ void __launch_bounds__(256, 2)
k_encoder(const float* __restrict__ X, const float* __restrict__ W, const float* __restrict__ Bv) {
    const int j = threadIdx.x, y = threadIdx.y;
    float w[64];
#pragma unroll
    for (int k = 0; k < 64; k++) w[k] = __ldg(W + k * 64 + j);
    const float bj = __ldg(Bv + j);
    __shared__ float xs[4][64];
    const int nT = (NN + 3) / 4;
    int per = (nT + gridDim.x - 1) / gridDim.x;
    int t0 = blockIdx.x * per, t1 = min(nT, t0 + per);
    if (t0 >= t1) return;
    int r0 = t0 * 4 + y;
    float pf = (r0 < NN) ? __ldg(X + (size_t)r0 * 64 + j) : 0.f;
    for (int tile = t0; tile < t1; ++tile) {
        __syncthreads();
        xs[y][j] = pf;
        __syncthreads();
        int nr = (tile + 1) * 4 + y;
        if (tile + 1 < t1) pf = (nr < NN) ? __ldg(X + (size_t)nr * 64 + j) : 0.f;
        int r = tile * 4 + y;
        if (r < NN) {
            float a0 = 0.f, a1 = 0.f, a2 = 0.f, a3 = 0.f;
#pragma unroll
            for (int k = 0; k < 64; k += 4) {
                a0 = fmaf(xs[y][k],     w[k],     a0);
                a1 = fmaf(xs[y][k + 1], w[k + 1], a1);
                a2 = fmaf(xs[y][k + 2], w[k + 2], a2);
                a3 = fmaf(xs[y][k + 3], w[k + 3], a3);
            }
            g_h[(size_t)r * 64 + j] = (a0 + a1) + (a2 + a3) + bj;
        }
    }
}

// ---------------- scatter: S[dst] += h[src]   (thread = (edge, float4 chunk)) ----------------
__global__ void k_scatter(const int* __restrict__ ei) {
    int t = blockIdx.x * 256 + threadIdx.x;
    if (t >= EE * 16) return;
    int e = t >> 4, q = t & 15;
    int s = __ldg(ei + e);
    int d = __ldg(ei + EE + e);
    float4 v = __ldg((const float4*)(g_h + (size_t)s * 64) + q);
    red4(&g_S[(size_t)d * 64 + q * 4], v);
}

// ---------------- fuse1: T = relu(h@A + S@B + agg_ea@C + c1 + deg*c2) ----------------
__global__ void __launch_bounds__(256, 1)
k_fuse1() {
    const int j = threadIdx.x, y = threadIdx.y;
    float wa[64], wb[64], wc[16];
#pragma unroll
    for (int k = 0; k < 64; k++) { wa[k] = g_A[k * 64 + j]; wb[k] = g_B[k * 64 + j]; }
#pragma unroll
    for (int k = 0; k < 16; k++) wc[k] = g_C[k * 64 + j];
    const float b1 = g_c1[j], b2 = g_c2[j];
    __shared__ float hs[4][64], Ss[4][64], eas[4][16], degs[4];
    const int nT = (NN + 3) / 4;
    int per = (nT + gridDim.x - 1) / gridDim.x;
    int t0 = blockIdx.x * per, t1 = min(nT, t0 + per);
    if (t0 >= t1) return;
    float ph = 0.f, pS = 0.f, pea = 0.f, pdeg = 0.f;
    {
        int r = t0 * 4 + y;
        if (r < NN) {
            ph = __ldg(g_h + (size_t)r * 64 + j);
            pS = __ldg(g_S + (size_t)r * 64 + j);
            if (j < 16) pea = __ldg(g_aggea + (size_t)r * 16 + j);
            if (j == 0) pdeg = __ldg(g_deg + r);
        }
    }
    for (int tile = t0; tile < t1; ++tile) {
        __syncthreads();
        hs[y][j] = ph;
        Ss[y][j] = pS;
        if (j < 16) eas[y][j] = pea;
        if (j == 0) degs[y] = pdeg;
        __syncthreads();
        int nr = (tile + 1) * 4 + y;
        if (tile + 1 < t1 && nr < NN) {
            ph = __ldg(g_h + (size_t)nr * 64 + j);
            pS = __ldg(g_S + (size_t)nr * 64 + j);
            if (j < 16) pea = __ldg(g_aggea + (size_t)nr * 16 + j);
            if (j == 0) pdeg = __ldg(g_deg + nr);
        }
        int r = tile * 4 + y;
        if (r < NN) {
            float u0 = 0.f, u1 = 0.f, u2 = 0.f, u3 = 0.f;
            float v0 = 0.f, v1 = 0.f, v2 = 0.f, v3 = 0.f;
#pragma unroll
            for (int k = 0; k < 64; k += 4) {
                u0 = fmaf(hs[y][k],     wa[k],     u0);
                u1 = fmaf(hs[y][k + 1], wa[k + 1], u1);
                u2 = fmaf(hs[y][k + 2], wa[k + 2], u2);
                u3 = fmaf(hs[y][k + 3], wa[k + 3], u3);
                v0 = fmaf(Ss[y][k],     wb[k],     v0);
                v1 = fmaf(Ss[y][k + 1], wb[k + 1], v1);
                v2 = fmaf(Ss[y][k + 2], wb[k + 2], v2);
                v3 = fmaf(Ss[y][k + 3], wb[k + 3], v3);
            }
#pragma unroll
            for (int k = 0; k < 16; k += 4) {
                u0 = fmaf(eas[y][k],     wc[k],     u0);
                u1 = fmaf(eas[y][k + 1], wc[k + 1], u1);
                u2 = fmaf(eas[y][k + 2], wc[k + 2], u2);
                u3 = fmaf(eas[y][k + 3], wc[k + 3], u3);
            }
            float val = ((u0 + u1) + (u2 + u3)) + ((v0 + v1) + (v2 + v3)) + b1 + degs[y] * b2;
            g_T[(size_t)r * 64 + j] = fmaxf(val, 0.f);
        }
    }
}

// ---------------- fuse2: tmp = T @ W2 + b2, plus GraphNorm stats (sorted batch, register carry) ----------------
__global__ void __launch_bounds__(256, 2)
k_fuse2(const float* __restrict__ W2, const float* __restrict__ b2, const int* __restrict__ batch) {
    const int j = threadIdx.x, y = threadIdx.y;
    float w[64];
#pragma unroll
    for (int k = 0; k < 64; k++) w[k] = __ldg(W2 + k * 64 + j);
    const float bj = __ldg(b2 + j);
    __shared__ float ts[4][64];
    const int nT = (NN + 3) / 4;
    int per = (nT + gridDim.x - 1) / gridDim.x;
    int t0 = blockIdx.x * per, t1 = min(nT, t0 + per);
    if (t0 >= t1) return;
    float cs = 0.f, cq = 0.f;
    int cg = -1;
    int r0 = t0 * 4 + y;
    float pf = (r0 < NN) ? __ldg(g_T + (size_t)r0 * 64 + j) : 0.f;
    for (int tile = t0; tile < t1; ++tile) {
        __syncthreads();
        ts[y][j] = pf;
        __syncthreads();
        int nr = (tile + 1) * 4 + y;
        if (tile + 1 < t1) pf = (nr < NN) ? __ldg(g_T + (size_t)nr * 64 + j) : 0.f;
        int r = tile * 4 + y;
        if (r < NN) {
            float a0 = 0.f, a1 = 0.f, a2 = 0.f, a3 = 0.f;
#pragma unroll
            for (int k = 0; k < 64; k += 4) {
                a0 = fmaf(ts[y][k],     w[k],     a0);
                a1 = fmaf(ts[y][k + 1], w[k + 1], a1);
                a2 = fmaf(ts[y][k + 2], w[k + 2], a2);
                a3 = fmaf(ts[y][k + 3], w[k + 3], a3);
            }
            float v = (a0 + a1) + (a2 + a3) + bj;
            g_tmp[(size_t)r * 64 + j] = v;
            int g = __ldg(batch + r);
            if (g != cg) {
                if (cg >= 0) {
                    atomicAdd(&g_sum[cg * 64 + j], cs);
                    atomicAdd(&g_sumsq[cg * 64 + j], cq);
                }
                cg = g; cs = 0.f; cq = 0.f;
            }
            cs += v;
            cq += v * v;
        }
    }
    if (cg >= 0) {
        atomicAdd(&g_sum[cg * 64 + j], cs);
        atomicAdd(&g_sumsq[cg * 64 + j], cq);
    }
}

__global__ void k_fin() {
    int i = blockIdx.x * blockDim.x + threadIdx.x;
    if (i >= GG * HH) return;
    int g = i >> 6;
    float c = fmaxf(g_cnt[g], 1.0f);
    float m = g_sum[i] / c;
    float v = g_sumsq[i] / c - m * m;
    g_mean[i] = m;
    g_istd[i] = rsqrtf(v + 1e-5f);
}

// h_new = relu(w * (tmp - mean)*istd + b) + h_old     (out==nullptr -> write g_h, else d_out)
__global__ void k_norm(const int* __restrict__ batch, const float* __restrict__ nw,
                       const float* __restrict__ nb, float* __restrict__ out) {
    int i = blockIdx.x * blockDim.x + threadIdx.x;
    if (i >= NN * 16) return;
    int n = i >> 4, q = i & 15;
    int g = __ldg(batch + n);
    float4 t  = *((const float4*)g_tmp + i);
    float4 m  = *((const float4*)g_mean + g * 16 + q);
    float4 is = *((const float4*)g_istd + g * 16 + q);
    float4 w  = __ldg((const float4*)nw + q);
    float4 b  = __ldg((const float4*)nb + q);
    float4 r  = *((const float4*)g_h + i);
    float4 o;
    o.x = fmaxf(fmaf(w.x, (t.x - m.x) * is.x, b.x), 0.f) + r.x;
    o.y = fmaxf(fmaf(w.y, (t.y - m.y) * is.y, b.y), 0.f) + r.y;
    o.z = fmaxf(fmaf(w.z, (t.z - m.z) * is.z, b.z), 0.f) + r.z;
    o.w = fmaxf(fmaf(w.w, (t.w - m.w) * is.w, b.w), 0.f) + r.w;
    float4* dst = out ? (float4*)out : (float4*)g_h;
    dst[i] = o;
}

// ---------------- launch ----------------
extern "C" void kernel_launch(void* const* d_in, const int* in_sizes, int n_in,
                              void* d_out, int out_size) {
    const float* x     = (const float*)d_in[0];
    const int*   ei    = (const int*)  d_in[1];
    const float* ea    = (const float*)d_in[2];
    const int*   batch = (const int*)  d_in[3];
    const float* encW  = (const float*)d_in[4];
    const float* encb  = (const float*)d_in[5];
    const float* nodeW = (const float*)d_in[6];
    const float* nodeb = (const float*)d_in[7];
    const float* edgeW = (const float*)d_in[8];
    const float* edgeb = (const float*)d_in[9];
    const float* m1W   = (const float*)d_in[10];
    const float* m1b   = (const float*)d_in[11];
    const float* m2W   = (const float*)d_in[12];
    const float* m2b   = (const float*)d_in[13];
    const float* nw    = (const float*)d_in[14];
    const float* nb    = (const float*)d_in[15];

    dim3 blk(64, 4);
    const int GRID = 1184;

    k_zero_init<<<2048, 256>>>();
    k_edge_pre<<<(EE * 4 + 255) / 256, 256>>>(ei, ea);
    k_cnt<<<(NN + 255) / 256, 256>>>(batch);
    k_encoder<<<GRID, blk>>>(x, encW, encb);

    for (int l = 0; l < LL; l++) {
        k_pre<<<81 + 64, 64>>>(nodeW + l * 4096, edgeW + l * 1024,
                               nodeb + l * 64, edgeb + l * 64,
                               m1W + l * 8192, m1b + l * 64);
        k_zero_layer<<<2048, 256>>>();
        k_scatter<<<(EE * 16 + 255) / 256, 256>>>(ei);
        k_fuse1<<<GRID, blk>>>();
        k_fuse2<<<GRID, blk>>>(m2W + l * 4096, m2b + l * 64, batch);
        k_fin<<<(GG * HH + 255) / 256, 256>>>();
        k_norm<<<(NN * 16 + 255) / 256, 256>>>(batch, nw + l * 64, nb + l * 64,
                                               (l == LL - 1) ? (float*)d_out : nullptr);
    }
}